// round 13
// baseline (speedup 1.0000x reference)
#include <cuda_runtime.h>
#include <stdint.h>

#define NPTS 500000
#define KK 27

// Scratch (allocation-free rule: __device__ globals)
__device__ float g_h0 [NPTS * 32];
__device__ float g_h0c[NPTS * 32];
__device__ float g_h1 [NPTS * 32];
__device__ int   g_midxT[(size_t)KK * NPTS];   // transposed masked idx: [k][p]

// Permuted tf32 weights, fragment-ordered (R5 layout).
#define WP10_OFF 0
#define WP01_OFF 27648
#define WP11_OFF (27648 + 6912)
#define WP00_OFF (27648 + 6912 + 13824)
#define WP02_OFF (27648 + 6912 + 13824 + 1024)
__device__ uint4 g_wperm[27648 + 6912 + 13824 + 1024 + 512];

// ---------------------------------------------------------------------------
__device__ __forceinline__ uint32_t f2tf32(float v) {
    uint32_t r;
    asm("cvt.rna.tf32.f32 %0, %1;" : "=r"(r) : "f"(v));
    return r;
}

__device__ __forceinline__ void mma_16n8k8(float* c, uint32_t a0, uint32_t a1,
                                           uint32_t a2, uint32_t a3,
                                           uint32_t b0, uint32_t b1) {
    asm volatile(
        "mma.sync.aligned.m16n8k8.row.col.f32.tf32.tf32.f32 "
        "{%0,%1,%2,%3}, {%4,%5,%6,%7}, {%8,%9}, {%0,%1,%2,%3};"
        : "+f"(c[0]), "+f"(c[1]), "+f"(c[2]), "+f"(c[3])
        : "r"(a0), "r"(a1), "r"(a2), "r"(a3), "r"(b0), "r"(b1));
}

// ---------------------------------------------------------------------------
// Weight permutation prep (R5 fragment layout, KKT taps).
// ---------------------------------------------------------------------------
template <int CIN, int COUT, int KKT>
__global__ void k_permW(const float* __restrict__ W, uint4* __restrict__ dst)
{
    const int PAIRS = CIN / 16, NTS = COUT / 8;
    const int total = KKT * PAIRS * NTS * 32;
    const int s = blockIdx.x * 256 + threadIdx.x;
    if (s >= total) return;
    const int lane = s & 31;
    int t = s >> 5;
    const int nt = t % NTS; t /= NTS;
    const int pr = t % PAIRS; t /= PAIRS;
    const int k = t;
    const int four = lane & 3, grp = lane >> 2;
    const int col = nt * 8 + grp;
    const int r0 = pr * 16 + four;
    const size_t base = (size_t)k * CIN * COUT + col;
    uint4 v;
    v.x = f2tf32(W[base + (size_t)(r0)      * COUT]);
    v.y = f2tf32(W[base + (size_t)(r0 + 4)  * COUT]);
    v.z = f2tf32(W[base + (size_t)(r0 + 8)  * COUT]);
    v.w = f2tf32(W[base + (size_t)(r0 + 12) * COUT]);
    dst[s] = v;
}

// ---------------------------------------------------------------------------
// Masked-neighbor transpose prep: midxT[k][p] = mask[p][k] ? nbr[p][k] : -1.
// ---------------------------------------------------------------------------
__global__ __launch_bounds__(256) void k_midx(const int* __restrict__ nbr,
                                              const int* __restrict__ mask,
                                              int* __restrict__ midxT)
{
    __shared__ int tile[128 * KK];
    const int tid = threadIdx.x;
    const int pbase = blockIdx.x * 128;
    for (int i = tid; i < 128 * KK; i += 256) {
        const int p = pbase + i / KK;
        int v = -1;
        if (p < NPTS) {
            const size_t g = (size_t)pbase * KK + i;
            if (mask[g] != 0) v = nbr[g];
        }
        tile[i] = v;
    }
    __syncthreads();
    for (int i = tid; i < 128 * KK; i += 256) {
        const int k = i >> 7, j = i & 127;
        if (pbase + j < NPTS)
            midxT[(size_t)k * NPTS + pbase + j] = tile[j * KK + k];
    }
}

// ---------------------------------------------------------------------------
// Sparse-conv GEMM via mma.sync tf32 with SMEM-STAGED A (coalesced gather).
// Block: 256 threads = 8 warps; 128 points/block; warp owns one m16 tile.
// Per k: rows gathered contiguously (float4 per lane, warp-aligned rows) into
// padded A-tile (RS = CIN+4 floats, RS%32==4 -> conflict-free fragment LDS),
// B slab staged as before; fragments fed from smem.
// MODE 0: out[N,COUT] = relu(acc + b)
// MODE 1: out[N,128] cols [64,128) = acc + b + x[:,64:128)   (COUT=64)
// MODE 2: out[N,128] cols [0,64)   = acc + b + x[:,0:64)     (COUT=64)
// ---------------------------------------------------------------------------
template <int CIN, int COUT, int MODE, int GATHER>
__global__ __launch_bounds__(256) void k_conv_mma(
    const float* __restrict__ f, const int* __restrict__ midxT,
    const uint4* __restrict__ Wp, const float* __restrict__ b,
    const float* __restrict__ x, float* __restrict__ out)
{
    constexpr int PAIRS = CIN / 16, NTS = COUT / 8;
    constexpr int KT    = GATHER ? KK : 1;
    constexpr int RS    = CIN + 4;            // row stride (floats), RS%32==4
    constexpr int slabN = PAIRS * NTS * 32;   // uint4 per k
    constexpr int C4    = CIN / 4;

    extern __shared__ __align__(16) float smem[];
    float* As  = smem;                          // 128 * RS floats
    uint4* Bs4 = (uint4*)(smem + 128 * RS);     // slabN uint4
    float* bs  = (float*)(Bs4 + slabN);         // COUT floats

    const int tid  = threadIdx.x;
    const int warp = tid >> 5;
    const int lane = tid & 31;
    const int grp  = lane >> 2;
    const int four = lane & 3;

    if (tid < COUT) bs[tid] = b[tid];

    const int pbase = blockIdx.x * 128;
    const int lr0   = warp * 16 + grp;          // local rows lr0, lr0+8

    float acc[NTS][4];
#pragma unroll
    for (int nt = 0; nt < NTS; nt++)
#pragma unroll
        for (int j = 0; j < 4; j++) acc[nt][j] = 0.f;

    for (int k = 0; k < KT; k++) {
        __syncthreads();                         // prev compute done
        // stage B slab (coalesced LDG.128, conflict-free STS)
        for (int i = tid; i < slabN; i += 256)
            Bs4[i] = Wp[(size_t)k * slabN + i];
        // stage A: coalesced row gather (warp-aligned rows, float4/lane)
#pragma unroll 4
        for (int i = tid; i < 128 * C4; i += 256) {
            const int row = i / C4;
            const int c4  = i % C4;
            const int p   = pbase + row;
            int idx;
            if (GATHER) idx = (p < NPTS) ? __ldg(midxT + (size_t)k * NPTS + p) : -1;
            else        idx = (p < NPTS) ? p : -1;
            float4 v = make_float4(0.f, 0.f, 0.f, 0.f);
            if (idx >= 0)
                v = *reinterpret_cast<const float4*>(f + (size_t)idx * CIN + c4 * 4);
            *reinterpret_cast<float4*>(As + row * RS + c4 * 4) = v;
        }
        __syncthreads();                         // tiles visible

        // compute from smem
#pragma unroll
        for (int pr = 0; pr < PAIRS; pr++) {
            const int base0 = lr0 * RS + pr * 16 + four;
            const int base1 = base0 + 8 * RS;
            uint32_t A0[4], A1[4];
#pragma unroll
            for (int j = 0; j < 4; j++) {
                A0[j] = f2tf32(As[base0 + 4 * j]);
                A1[j] = f2tf32(As[base1 + 4 * j]);
            }
#pragma unroll
            for (int nt = 0; nt < NTS; nt++) {
                const uint4 B = Bs4[(pr * NTS + nt) * 32 + lane];
                mma_16n8k8(acc[nt], A0[0], A1[0], A0[1], A1[1], B.x, B.y);
                mma_16n8k8(acc[nt], A0[2], A1[2], A0[3], A1[3], B.z, B.w);
            }
        }
    }

    // epilogue: acc[nt][0,1] -> row lr0 ; acc[nt][2,3] -> row lr0+8
#pragma unroll
    for (int half = 0; half < 2; half++) {
        const int p = pbase + lr0 + half * 8;
        if (p >= NPTS) continue;
#pragma unroll
        for (int nt = 0; nt < NTS; nt++) {
            const float c0 = acc[nt][half * 2];
            const float c1 = acc[nt][half * 2 + 1];
            const int col = nt * 8 + 2 * four;
            if (MODE == 0) {
                float2 v = {fmaxf(c0 + bs[col], 0.f), fmaxf(c1 + bs[col + 1], 0.f)};
                *reinterpret_cast<float2*>(out + (size_t)p * COUT + col) = v;
            } else {
                const int oc = (MODE == 1) ? (64 + col) : col;
                const size_t a = (size_t)p * 128 + oc;
                float2 xr = *reinterpret_cast<const float2*>(x + a);
                float2 v = {c0 + bs[col] + xr.x, c1 + bs[col + 1] + xr.y};
                *reinterpret_cast<float2*>(out + a) = v;
            }
        }
    }
}

// ---------------------------------------------------------------------------
static inline int smem_bytes(int CIN, int COUT) {
    return 128 * (CIN + 4) * 4 + CIN * COUT * 4 + COUT * 4 + 16;
}

extern "C" void kernel_launch(void* const* d_in, const int* in_sizes, int n_in,
                              void* d_out, int out_size)
{
    const float* x    = (const float*)d_in[0];
    const int*   nbr  = (const int*)  d_in[1];
    const int*   mask = (const int*)  d_in[2];   // bool -> int32 in harness
    const float* W00  = (const float*)d_in[3];
    const float* b00  = (const float*)d_in[4];
    const float* W01  = (const float*)d_in[5];
    const float* b01  = (const float*)d_in[6];
    const float* W02  = (const float*)d_in[7];
    const float* b02  = (const float*)d_in[8];
    const float* W10  = (const float*)d_in[9];
    const float* b10  = (const float*)d_in[10];
    const float* W11  = (const float*)d_in[11];
    const float* b11  = (const float*)d_in[12];
    float* out = (float*)d_out;

    float *h0, *h0c, *h1;
    int* midxT;
    uint4* wp;
    cudaGetSymbolAddress((void**)&h0,    g_h0);
    cudaGetSymbolAddress((void**)&h0c,   g_h0c);
    cudaGetSymbolAddress((void**)&h1,    g_h1);
    cudaGetSymbolAddress((void**)&midxT, g_midxT);
    cudaGetSymbolAddress((void**)&wp,    g_wperm);

    const int SM_A = smem_bytes(128, 32);   // ~84KB: conv W10 + 1x1 W00
    const int SM_B = smem_bytes(32, 32);    // ~23KB: conv W01
    const int SM_C = smem_bytes(32, 64);    // ~27KB: conv W11 + 1x1 W02
    cudaFuncSetAttribute(k_conv_mma<128, 32, 0, 1>, cudaFuncAttributeMaxDynamicSharedMemorySize, SM_A);
    cudaFuncSetAttribute(k_conv_mma<128, 32, 0, 0>, cudaFuncAttributeMaxDynamicSharedMemorySize, SM_A);
    cudaFuncSetAttribute(k_conv_mma< 32, 32, 0, 1>, cudaFuncAttributeMaxDynamicSharedMemorySize, SM_B);
    cudaFuncSetAttribute(k_conv_mma< 32, 64, 2, 0>, cudaFuncAttributeMaxDynamicSharedMemorySize, SM_C);
    cudaFuncSetAttribute(k_conv_mma< 32, 64, 1, 1>, cudaFuncAttributeMaxDynamicSharedMemorySize, SM_C);

    const int blocks = (NPTS + 127) / 128;

    // launches 0..2: prep needed by the big conv
    k_permW<128, 32, KK><<<(27648 + 255) / 256, 256>>>(W10, wp + WP10_OFF);
    k_permW< 32, 32, KK><<<( 6912 + 255) / 256, 256>>>(W01, wp + WP01_OFF);
    k_midx<<<blocks, 256>>>(nbr, mask, midxT);

    // launch 3 (ncu capture slot): branch 1 heavy conv3 -> relu
    k_conv_mma<128, 32, 0, 1><<<blocks, 256, SM_A>>>(x, midxT, wp + WP10_OFF, b10, nullptr, h1);

    // remaining prep
    k_permW< 32, 64, KK><<<(13824 + 255) / 256, 256>>>(W11, wp + WP11_OFF);
    k_permW<128, 32,  1><<<( 1024 + 255) / 256, 256>>>(W00, wp + WP00_OFF);
    k_permW< 32, 64,  1><<<(  512 + 255) / 256, 256>>>(W02, wp + WP02_OFF);

    // branch 0: 1x1 -> relu
    k_conv_mma<128, 32, 0, 0><<<blocks, 256, SM_A>>>(x, nullptr, wp + WP00_OFF, b00, nullptr, h0);
    // branch 0: 3x3 -> relu
    k_conv_mma<32, 32, 0, 1><<<blocks, 256, SM_B>>>(h0, midxT, wp + WP01_OFF, b01, nullptr, h0c);
    // branch 0 tail: 1x1 + bias + residual -> out[:, 0:64)
    k_conv_mma<32, 64, 2, 0><<<blocks, 256, SM_C>>>(h0c, nullptr, wp + WP02_OFF, b02, x, out);
    // branch 1 tail: 3x3 + bias + residual -> out[:, 64:128)
    k_conv_mma<32, 64, 1, 1><<<blocks, 256, SM_C>>>(h1, midxT, wp + WP11_OFF, b11, x, out);
}

// round 14
// speedup vs baseline: 2.8072x; 2.8072x over previous
#include <cuda_runtime.h>
#include <cuda_fp16.h>
#include <stdint.h>

#define NPTS 500000
#define KK 27

// Scratch (allocation-free rule: __device__ globals)
__device__ __half g_xh [(size_t)NPTS * 128];  // fp16 x
__device__ __half g_h0 [NPTS * 32];
__device__ __half g_h0c[NPTS * 32];
__device__ __half g_h1 [NPTS * 32];
__device__ int    g_midxT[(size_t)KK * NPTS]; // transposed masked idx: [k][p]

// Permuted fp16 weights, m16n8k16-fragment-ordered:
//   slot s = ((k*PAIRS + pr)*NTS + nt)*32 + lane, uint2 =
//   { half2(W[k][pr*16+2f][col],   W[k][pr*16+2f+1][col]),
//     half2(W[k][pr*16+8+2f][col], W[k][pr*16+9+2f][col]) },  f=lane&3, col=nt*8+(lane>>2)
#define WP10_OFF 0
#define WP01_OFF 27648
#define WP11_OFF (27648 + 6912)
#define WP00_OFF (27648 + 6912 + 13824)
#define WP02_OFF (27648 + 6912 + 13824 + 1024)
__device__ uint2 g_wperm[27648 + 6912 + 13824 + 1024 + 512];

// ---------------------------------------------------------------------------
__device__ __forceinline__ uint32_t h2bits(__half2 h) {
    return *reinterpret_cast<uint32_t*>(&h);
}

__device__ __forceinline__ void mma_16n8k16(float* c, uint32_t a0, uint32_t a1,
                                            uint32_t a2, uint32_t a3,
                                            uint32_t b0, uint32_t b1) {
    asm volatile(
        "mma.sync.aligned.m16n8k16.row.col.f32.f16.f16.f32 "
        "{%0,%1,%2,%3}, {%4,%5,%6,%7}, {%8,%9}, {%0,%1,%2,%3};"
        : "+f"(c[0]), "+f"(c[1]), "+f"(c[2]), "+f"(c[3])
        : "r"(a0), "r"(a1), "r"(a2), "r"(a3), "r"(b0), "r"(b1));
}

// ---------------------------------------------------------------------------
// x -> fp16 prepass
// ---------------------------------------------------------------------------
__global__ __launch_bounds__(256) void k_cvt_x(const float4* __restrict__ x,
                                               uint2* __restrict__ xh)
{
    const int i = blockIdx.x * 256 + threadIdx.x;
    if (i >= NPTS * 32) return;
    float4 v = x[i];
    uint2 q;
    q.x = h2bits(__floats2half2_rn(v.x, v.y));
    q.y = h2bits(__floats2half2_rn(v.z, v.w));
    xh[i] = q;
}

// ---------------------------------------------------------------------------
// Weight permutation prep (fp16 fragment layout, KKT taps).
// ---------------------------------------------------------------------------
template <int CIN, int COUT, int KKT>
__global__ void k_permW(const float* __restrict__ W, uint2* __restrict__ dst)
{
    const int PAIRS = CIN / 16, NTS = COUT / 8;
    const int total = KKT * PAIRS * NTS * 32;
    const int s = blockIdx.x * 256 + threadIdx.x;
    if (s >= total) return;
    const int lane = s & 31;
    int t = s >> 5;
    const int nt = t % NTS; t /= NTS;
    const int pr = t % PAIRS; t /= PAIRS;
    const int k = t;
    const int four = lane & 3, grp = lane >> 2;
    const int col = nt * 8 + grp;
    const int c0 = pr * 16 + 2 * four;
    const size_t base = (size_t)k * CIN * COUT + col;
    uint2 v;
    v.x = h2bits(__floats2half2_rn(W[base + (size_t)(c0)     * COUT],
                                   W[base + (size_t)(c0 + 1) * COUT]));
    v.y = h2bits(__floats2half2_rn(W[base + (size_t)(c0 + 8) * COUT],
                                   W[base + (size_t)(c0 + 9) * COUT]));
    dst[s] = v;
}

// ---------------------------------------------------------------------------
// Masked-neighbor transpose prep: midxT[k][p] = mask[p][k] ? nbr[p][k] : -1.
// ---------------------------------------------------------------------------
__global__ __launch_bounds__(256) void k_midx(const int* __restrict__ nbr,
                                              const int* __restrict__ mask,
                                              int* __restrict__ midxT)
{
    __shared__ int tile[128 * KK];
    const int tid = threadIdx.x;
    const int pbase = blockIdx.x * 128;
    for (int i = tid; i < 128 * KK; i += 256) {
        const int p = pbase + i / KK;
        int v = -1;
        if (p < NPTS) {
            const size_t g = (size_t)pbase * KK + i;
            if (mask[g] != 0) v = nbr[g];
        }
        tile[i] = v;
    }
    __syncthreads();
    for (int i = tid; i < 128 * KK; i += 256) {
        const int k = i >> 7, j = i & 127;
        if (pbase + j < NPTS)
            midxT[(size_t)k * NPTS + pbase + j] = tile[j * KK + k];
    }
}

// ---------------------------------------------------------------------------
// Unified sparse-conv GEMM via mma.sync fp16 (R8 loop structure, m32/warp).
// Block: 256 threads = 8 warps; 256 points/block; warp owns 32 points
// (two m16 tiles: rows lr+{0,8} and lr+{16,24}, lr = warp*32 + grp).
// GATHER=1: 27-tap gather conv via midxT.  GATHER=0: 1x1 (KT=1).
// MODE 0: out = fp16[N,COUT] = relu(acc + b)
// MODE 1: out = f32[N,128] cols [64,128) = acc + b + x[:,64:128)  (COUT=64)
// MODE 2: out = f32[N,128] cols [0,64)   = acc + b + x[:,0:64)    (COUT=64)
// ---------------------------------------------------------------------------
template <int CIN, int COUT, int MODE, int GATHER>
__global__ __launch_bounds__(256) void k_conv_mma(
    const __half* __restrict__ f, const int* __restrict__ midxT,
    const uint2* __restrict__ Wp, const float* __restrict__ b,
    const float* __restrict__ x, void* __restrict__ outv)
{
    constexpr int PAIRS = CIN / 16, NTS = COUT / 8;
    constexpr int KT    = GATHER ? KK : 1;
    constexpr int slabN = PAIRS * NTS * 32;   // uint2 per k
    __shared__ uint2 Bs[slabN];
    __shared__ float bs[COUT];

    const int tid  = threadIdx.x;
    const int warp = tid >> 5;
    const int lane = tid & 31;
    const int grp  = lane >> 2;
    const int four = lane & 3;

    if (tid < COUT) bs[tid] = b[tid];

    const int pbase = blockIdx.x * 256;
    const int lr = warp * 32 + grp;           // lane's rows: lr+{0,8,16,24}

    float acc0[NTS][4], acc1[NTS][4];
#pragma unroll
    for (int nt = 0; nt < NTS; nt++)
#pragma unroll
        for (int j = 0; j < 4; j++) { acc0[nt][j] = 0.f; acc1[nt][j] = 0.f; }

    for (int k = 0; k < KT; k++) {
        __syncthreads();
        for (int i = tid; i < slabN; i += 256)
            Bs[i] = Wp[(size_t)k * slabN + i];
        __syncthreads();

        int idx[4];
#pragma unroll
        for (int r = 0; r < 4; r++) {
            const int p = pbase + lr + r * 8;
            if (GATHER) idx[r] = (p < NPTS) ? __ldg(midxT + (size_t)k * NPTS + p) : -1;
            else        idx[r] = (p < NPTS) ? p : NPTS - 1;   // clamp; store guarded
        }
        const uint32_t* rows[4];
#pragma unroll
        for (int r = 0; r < 4; r++)
            rows[r] = reinterpret_cast<const uint32_t*>(
                f + (size_t)(idx[r] < 0 ? 0 : idx[r]) * CIN);

#pragma unroll
        for (int pr = 0; pr < PAIRS; pr++) {
            uint32_t lo[4], hi[4];   // ch pr*16+2f pair ; ch pr*16+8+2f pair
#pragma unroll
            for (int r = 0; r < 4; r++) {
                if (!GATHER || idx[r] >= 0) {
                    const uint32_t* rp = rows[r] + pr * 8 + four;
                    lo[r] = __ldg(rp);
                    hi[r] = __ldg(rp + 4);
                } else {
                    lo[r] = 0u; hi[r] = 0u;
                }
            }
#pragma unroll
            for (int nt = 0; nt < NTS; nt++) {
                const uint2 B = Bs[(pr * NTS + nt) * 32 + lane];
                mma_16n8k16(acc0[nt], lo[0], lo[1], hi[0], hi[1], B.x, B.y);
                mma_16n8k16(acc1[nt], lo[2], lo[3], hi[2], hi[3], B.x, B.y);
            }
        }
    }

    // epilogue: acc0 -> rows lr, lr+8 ; acc1 -> rows lr+16, lr+24
#pragma unroll
    for (int t = 0; t < 2; t++) {
#pragma unroll
        for (int half = 0; half < 2; half++) {
            const int p = pbase + lr + t * 16 + half * 8;
            if (p >= NPTS) continue;
#pragma unroll
            for (int nt = 0; nt < NTS; nt++) {
                const float c0 = (t == 0) ? acc0[nt][half * 2]     : acc1[nt][half * 2];
                const float c1 = (t == 0) ? acc0[nt][half * 2 + 1] : acc1[nt][half * 2 + 1];
                const int col = nt * 8 + 2 * four;
                if (MODE == 0) {
                    // fp16 intermediate store (pair, 4B aligned)
                    uint32_t v = h2bits(__floats2half2_rn(fmaxf(c0 + bs[col], 0.f),
                                                          fmaxf(c1 + bs[col + 1], 0.f)));
                    *reinterpret_cast<uint32_t*>((__half*)outv + (size_t)p * COUT + col) = v;
                } else {
                    const int oc = (MODE == 1) ? (64 + col) : col;
                    const size_t a = (size_t)p * 128 + oc;
                    float2 xr = *reinterpret_cast<const float2*>(x + a);
                    float2 v = {c0 + bs[col] + xr.x, c1 + bs[col + 1] + xr.y};
                    *reinterpret_cast<float2*>((float*)outv + a) = v;
                }
            }
        }
    }
}

// ---------------------------------------------------------------------------
extern "C" void kernel_launch(void* const* d_in, const int* in_sizes, int n_in,
                              void* d_out, int out_size)
{
    const float* x    = (const float*)d_in[0];
    const int*   nbr  = (const int*)  d_in[1];
    const int*   mask = (const int*)  d_in[2];   // bool -> int32 in harness
    const float* W00  = (const float*)d_in[3];
    const float* b00  = (const float*)d_in[4];
    const float* W01  = (const float*)d_in[5];
    const float* b01  = (const float*)d_in[6];
    const float* W02  = (const float*)d_in[7];
    const float* b02  = (const float*)d_in[8];
    const float* W10  = (const float*)d_in[9];
    const float* b10  = (const float*)d_in[10];
    const float* W11  = (const float*)d_in[11];
    const float* b11  = (const float*)d_in[12];
    float* out = (float*)d_out;

    __half *xh, *h0, *h0c, *h1;
    int* midxT;
    uint2* wp;
    cudaGetSymbolAddress((void**)&xh,    g_xh);
    cudaGetSymbolAddress((void**)&h0,    g_h0);
    cudaGetSymbolAddress((void**)&h0c,   g_h0c);
    cudaGetSymbolAddress((void**)&h1,    g_h1);
    cudaGetSymbolAddress((void**)&midxT, g_midxT);
    cudaGetSymbolAddress((void**)&wp,    g_wperm);

    const int blocks  = (NPTS + 255) / 256;   // conv kernels: 256 points/block
    const int mblocks = (NPTS + 127) / 128;   // midx transpose tiles

    // launches 0..2: prep needed by the big conv
    k_permW<128, 32, KK><<<(27648 + 255) / 256, 256>>>(W10, wp + WP10_OFF);
    k_cvt_x<<<(NPTS * 32 + 255) / 256, 256>>>((const float4*)x, (uint2*)xh);
    k_midx<<<mblocks, 256>>>(nbr, mask, midxT);

    // launch 3 (ncu capture slot): branch 1 heavy conv3 -> relu
    k_conv_mma<128, 32, 0, 1><<<blocks, 256>>>(xh, midxT, wp + WP10_OFF, b10, nullptr, h1);

    // remaining prep
    k_permW< 32, 32, KK><<<( 6912 + 255) / 256, 256>>>(W01, wp + WP01_OFF);
    k_permW< 32, 64, KK><<<(13824 + 255) / 256, 256>>>(W11, wp + WP11_OFF);
    k_permW<128, 32,  1><<<( 1024 + 255) / 256, 256>>>(W00, wp + WP00_OFF);
    k_permW< 32, 64,  1><<<(  512 + 255) / 256, 256>>>(W02, wp + WP02_OFF);

    // branch 0: 1x1 -> relu
    k_conv_mma<128, 32, 0, 0><<<blocks, 256>>>(xh, nullptr, wp + WP00_OFF, b00, nullptr, h0);
    // branch 0: 3x3 -> relu
    k_conv_mma<32, 32, 0, 1><<<blocks, 256>>>(h0, midxT, wp + WP01_OFF, b01, nullptr, h0c);
    // branch 0 tail: 1x1 + bias + residual -> out[:, 0:64)
    k_conv_mma<32, 64, 2, 0><<<blocks, 256>>>(h0c, nullptr, wp + WP02_OFF, b02, x, out);
    // branch 1 tail: 3x3 + bias + residual -> out[:, 64:128)
    k_conv_mma<32, 64, 1, 1><<<blocks, 256>>>(h1, midxT, wp + WP11_OFF, b11, x, out);
}

// round 15
// speedup vs baseline: 3.1150x; 1.1096x over previous
#include <cuda_runtime.h>
#include <cuda_fp16.h>
#include <stdint.h>

#define NPTS 500000
#define KK 27

// Scratch (allocation-free rule: __device__ globals)
__device__ __half g_xh [(size_t)NPTS * 128];  // fp16 x
__device__ __half g_h0 [NPTS * 32];
__device__ __half g_h0c[NPTS * 32];
__device__ __half g_h1 [NPTS * 32];
__device__ int    g_midxT[(size_t)KK * NPTS]; // transposed masked idx: [k][p]

// Permuted fp16 weights, m16n8k16-fragment-ordered, channel-consecutive:
//   slot s = ((k*PAIRS + pr)*NTS + nt)*32 + lane, uint2 =
//   { half2(W[c0],W[c0+1]), half2(W[c0+2],W[c0+3]) },  c0 = pr*16 + 4*(lane&3),
//   col = nt*8 + (lane>>2).
// A-side: lane f loads ONE uint2 (channels 4f..4f+3) per row per pr.
#define WP10_OFF 0
#define WP01_OFF 27648
#define WP11_OFF (27648 + 6912)
#define WP00_OFF (27648 + 6912 + 13824)
#define WP02_OFF (27648 + 6912 + 13824 + 1024)
__device__ uint2 g_wperm[27648 + 6912 + 13824 + 1024 + 512];

// ---------------------------------------------------------------------------
__device__ __forceinline__ uint32_t h2bits(__half2 h) {
    return *reinterpret_cast<uint32_t*>(&h);
}

__device__ __forceinline__ void mma_16n8k16(float* c, uint32_t a0, uint32_t a1,
                                            uint32_t a2, uint32_t a3,
                                            uint32_t b0, uint32_t b1) {
    asm volatile(
        "mma.sync.aligned.m16n8k16.row.col.f32.f16.f16.f32 "
        "{%0,%1,%2,%3}, {%4,%5,%6,%7}, {%8,%9}, {%0,%1,%2,%3};"
        : "+f"(c[0]), "+f"(c[1]), "+f"(c[2]), "+f"(c[3])
        : "r"(a0), "r"(a1), "r"(a2), "r"(a3), "r"(b0), "r"(b1));
}

// ---------------------------------------------------------------------------
// x -> fp16 prepass
// ---------------------------------------------------------------------------
__global__ __launch_bounds__(256) void k_cvt_x(const float4* __restrict__ x,
                                               uint2* __restrict__ xh)
{
    const int i = blockIdx.x * 256 + threadIdx.x;
    if (i >= NPTS * 32) return;
    float4 v = x[i];
    uint2 q;
    q.x = h2bits(__floats2half2_rn(v.x, v.y));
    q.y = h2bits(__floats2half2_rn(v.z, v.w));
    xh[i] = q;
}

// ---------------------------------------------------------------------------
// Weight permutation prep (channel-consecutive fragment layout, KKT taps).
// ---------------------------------------------------------------------------
template <int CIN, int COUT, int KKT>
__global__ void k_permW(const float* __restrict__ W, uint2* __restrict__ dst)
{
    const int PAIRS = CIN / 16, NTS = COUT / 8;
    const int total = KKT * PAIRS * NTS * 32;
    const int s = blockIdx.x * 256 + threadIdx.x;
    if (s >= total) return;
    const int lane = s & 31;
    int t = s >> 5;
    const int nt = t % NTS; t /= NTS;
    const int pr = t % PAIRS; t /= PAIRS;
    const int k = t;
    const int four = lane & 3, grp = lane >> 2;
    const int col = nt * 8 + grp;
    const int c0 = pr * 16 + 4 * four;
    const size_t base = (size_t)k * CIN * COUT + col;
    uint2 v;
    v.x = h2bits(__floats2half2_rn(W[base + (size_t)(c0)     * COUT],
                                   W[base + (size_t)(c0 + 1) * COUT]));
    v.y = h2bits(__floats2half2_rn(W[base + (size_t)(c0 + 2) * COUT],
                                   W[base + (size_t)(c0 + 3) * COUT]));
    dst[s] = v;
}

// ---------------------------------------------------------------------------
// Masked-neighbor transpose prep: midxT[k][p] = mask[p][k] ? nbr[p][k] : -1.
// ---------------------------------------------------------------------------
__global__ __launch_bounds__(256) void k_midx(const int* __restrict__ nbr,
                                              const int* __restrict__ mask,
                                              int* __restrict__ midxT)
{
    __shared__ int tile[128 * KK];
    const int tid = threadIdx.x;
    const int pbase = blockIdx.x * 128;
    for (int i = tid; i < 128 * KK; i += 256) {
        const int p = pbase + i / KK;
        int v = -1;
        if (p < NPTS) {
            const size_t g = (size_t)pbase * KK + i;
            if (mask[g] != 0) v = nbr[g];
        }
        tile[i] = v;
    }
    __syncthreads();
    for (int i = tid; i < 128 * KK; i += 256) {
        const int k = i >> 7, j = i & 127;
        if (pbase + j < NPTS)
            midxT[(size_t)k * NPTS + pbase + j] = tile[j * KK + k];
    }
}

// ---------------------------------------------------------------------------
// Unified sparse-conv GEMM via mma.sync fp16.
// Block: 256 threads = 8 warps; 256 points/block; warp owns 32 points
// (two m16 tiles: rows lr+{0,8} and lr+{16,24}).
// ALLK=1: all KK B slabs resident in smem -> NO barriers in k loop.
// ALLK=0: double-buffered B, one barrier per k (stage k+1 during compute k).
// A loads: one uint2 per row per pr, batched 2 pr at a time.
// MODE 0: fp16 out = relu(acc+b).  MODE 1/2: f32 out cols [64,128)/[0,64)
//         = acc + b + x residual.
// ---------------------------------------------------------------------------
template <int CIN, int COUT, int MODE, int GATHER, int ALLK>
__global__ __launch_bounds__(256) void k_conv_mma(
    const __half* __restrict__ f, const int* __restrict__ midxT,
    const uint2* __restrict__ Wp, const float* __restrict__ b,
    const float* __restrict__ x, void* __restrict__ outv)
{
    constexpr int PAIRS = CIN / 16, NTS = COUT / 8;
    constexpr int KT    = GATHER ? KK : 1;
    constexpr int slabN = PAIRS * NTS * 32;   // uint2 per k
    constexpr int NB    = ALLK ? KT : 2;

    extern __shared__ __align__(16) char smraw[];
    uint2* Bs = (uint2*)smraw;                 // NB * slabN
    float* bs = (float*)(Bs + NB * slabN);     // COUT

    const int tid  = threadIdx.x;
    const int warp = tid >> 5;
    const int lane = tid & 31;
    const int grp  = lane >> 2;
    const int four = lane & 3;

    if (tid < COUT) bs[tid] = b[tid];

    // initial B staging
    if (ALLK) {
        for (int i = tid; i < KT * slabN; i += 256) Bs[i] = Wp[i];
    } else {
        for (int i = tid; i < slabN; i += 256) Bs[i] = Wp[i];   // k=0 -> buf0
    }
    __syncthreads();

    const int pbase = blockIdx.x * 256;
    const int lr = warp * 32 + grp;           // lane's rows: lr+{0,8,16,24}

    float acc0[NTS][4], acc1[NTS][4];
#pragma unroll
    for (int nt = 0; nt < NTS; nt++)
#pragma unroll
        for (int j = 0; j < 4; j++) { acc0[nt][j] = 0.f; acc1[nt][j] = 0.f; }

    for (int k = 0; k < KT; k++) {
        const uint2* Bk = Bs + (ALLK ? k : (k & 1)) * slabN;
        // stage next slab into the other buffer (no sync yet)
        if (!ALLK && k + 1 < KT) {
            uint2* Bn = Bs + ((k + 1) & 1) * slabN;
            for (int i = tid; i < slabN; i += 256)
                Bn[i] = Wp[(size_t)(k + 1) * slabN + i];
        }

        int idx[4];
#pragma unroll
        for (int r = 0; r < 4; r++) {
            const int p = pbase + lr + r * 8;
            if (GATHER) idx[r] = (p < NPTS) ? __ldg(midxT + (size_t)k * NPTS + p) : -1;
            else        idx[r] = (p < NPTS) ? p : NPTS - 1;   // clamp; store guarded
        }
        const uint2* rows[4];
#pragma unroll
        for (int r = 0; r < 4; r++)
            rows[r] = reinterpret_cast<const uint2*>(
                f + (size_t)(idx[r] < 0 ? 0 : idx[r]) * CIN);

        // 2-pr batches: 8 independent loads in flight, then MMAs
#pragma unroll
        for (int h = 0; h < PAIRS / 2; h++) {
            uint2 A[2][4];
#pragma unroll
            for (int j = 0; j < 2; j++)
#pragma unroll
                for (int r = 0; r < 4; r++) {
                    if (!GATHER || idx[r] >= 0)
                        A[j][r] = __ldg(rows[r] + (h * 2 + j) * 4 + four);
                    else
                        A[j][r] = make_uint2(0u, 0u);
                }
#pragma unroll
            for (int j = 0; j < 2; j++) {
                const int pr = h * 2 + j;
#pragma unroll
                for (int nt = 0; nt < NTS; nt++) {
                    const uint2 B = Bk[(pr * NTS + nt) * 32 + lane];
                    mma_16n8k16(acc0[nt], A[j][0].x, A[j][1].x, A[j][0].y, A[j][1].y, B.x, B.y);
                    mma_16n8k16(acc1[nt], A[j][2].x, A[j][3].x, A[j][2].y, A[j][3].y, B.x, B.y);
                }
            }
        }
        if (!ALLK && k + 1 < KT) __syncthreads();
    }

    // epilogue: acc0 -> rows lr, lr+8 ; acc1 -> rows lr+16, lr+24
#pragma unroll
    for (int t = 0; t < 2; t++) {
#pragma unroll
        for (int half = 0; half < 2; half++) {
            const int p = pbase + lr + t * 16 + half * 8;
            if (p >= NPTS) continue;
#pragma unroll
            for (int nt = 0; nt < NTS; nt++) {
                const float c0 = (t == 0) ? acc0[nt][half * 2]     : acc1[nt][half * 2];
                const float c1 = (t == 0) ? acc0[nt][half * 2 + 1] : acc1[nt][half * 2 + 1];
                const int col = nt * 8 + 2 * four;
                if (MODE == 0) {
                    uint32_t v = h2bits(__floats2half2_rn(fmaxf(c0 + bs[col], 0.f),
                                                          fmaxf(c1 + bs[col + 1], 0.f)));
                    *reinterpret_cast<uint32_t*>((__half*)outv + (size_t)p * COUT + col) = v;
                } else {
                    const int oc = (MODE == 1) ? (64 + col) : col;
                    const size_t a = (size_t)p * 128 + oc;
                    float2 xr = *reinterpret_cast<const float2*>(x + a);
                    float2 v = {c0 + bs[col] + xr.x, c1 + bs[col + 1] + xr.y};
                    *reinterpret_cast<float2*>((float*)outv + a) = v;
                }
            }
        }
    }
}

// ---------------------------------------------------------------------------
extern "C" void kernel_launch(void* const* d_in, const int* in_sizes, int n_in,
                              void* d_out, int out_size)
{
    const float* x    = (const float*)d_in[0];
    const int*   nbr  = (const int*)  d_in[1];
    const int*   mask = (const int*)  d_in[2];   // bool -> int32 in harness
    const float* W00  = (const float*)d_in[3];
    const float* b00  = (const float*)d_in[4];
    const float* W01  = (const float*)d_in[5];
    const float* b01  = (const float*)d_in[6];
    const float* W02  = (const float*)d_in[7];
    const float* b02  = (const float*)d_in[8];
    const float* W10  = (const float*)d_in[9];
    const float* b10  = (const float*)d_in[10];
    const float* W11  = (const float*)d_in[11];
    const float* b11  = (const float*)d_in[12];
    float* out = (float*)d_out;

    __half *xh, *h0, *h0c, *h1;
    int* midxT;
    uint2* wp;
    cudaGetSymbolAddress((void**)&xh,    g_xh);
    cudaGetSymbolAddress((void**)&h0,    g_h0);
    cudaGetSymbolAddress((void**)&h0c,   g_h0c);
    cudaGetSymbolAddress((void**)&h1,    g_h1);
    cudaGetSymbolAddress((void**)&midxT, g_midxT);
    cudaGetSymbolAddress((void**)&wp,    g_wperm);

    // dynamic smem: NB*slabN*8 + COUT*4
    const int SM_BIG  = 2 * 1024 * 8 + 128;          // 16512: CIN=128 kernels
    const int SM_ALLK = KK * 256 * 8 + 128;          // 55424: CIN=32,COUT=32 conv
    const int SM_C64  = 2 * 512 * 8 + 256;           // 8448:  CIN=32,COUT=64 kernels
    cudaFuncSetAttribute(k_conv_mma<32, 32, 0, 1, 1>,
                         cudaFuncAttributeMaxDynamicSharedMemorySize, SM_ALLK);

    const int blocks  = (NPTS + 255) / 256;   // conv kernels: 256 points/block
    const int mblocks = (NPTS + 127) / 128;   // midx transpose tiles

    // launches 0..2: prep needed by the big conv
    k_permW<128, 32, KK><<<(27648 + 255) / 256, 256>>>(W10, wp + WP10_OFF);
    k_cvt_x<<<(NPTS * 32 + 255) / 256, 256>>>((const float4*)x, (uint2*)xh);
    k_midx<<<mblocks, 256>>>(nbr, mask, midxT);

    // launch 3 (ncu capture slot): branch 1 heavy conv3 -> relu
    k_conv_mma<128, 32, 0, 1, 0><<<blocks, 256, SM_BIG>>>(xh, midxT, wp + WP10_OFF, b10, nullptr, h1);

    // remaining prep
    k_permW< 32, 32, KK><<<( 6912 + 255) / 256, 256>>>(W01, wp + WP01_OFF);
    k_permW< 32, 64, KK><<<(13824 + 255) / 256, 256>>>(W11, wp + WP11_OFF);
    k_permW<128, 32,  1><<<( 1024 + 255) / 256, 256>>>(W00, wp + WP00_OFF);
    k_permW< 32, 64,  1><<<(  512 + 255) / 256, 256>>>(W02, wp + WP02_OFF);

    // branch 0: 1x1 -> relu
    k_conv_mma<128, 32, 0, 0, 0><<<blocks, 256, SM_BIG>>>(xh, nullptr, wp + WP00_OFF, b00, nullptr, h0);
    // branch 0: 3x3 -> relu  (all-k B resident, barrier-free k loop)
    k_conv_mma<32, 32, 0, 1, 1><<<blocks, 256, SM_ALLK>>>(h0, midxT, wp + WP01_OFF, b01, nullptr, h0c);
    // branch 0 tail: 1x1 + bias + residual -> out[:, 0:64)
    k_conv_mma<32, 64, 2, 0, 0><<<blocks, 256, SM_C64>>>(h0c, nullptr, wp + WP02_OFF, b02, x, out);
    // branch 1 tail: 3x3 + bias + residual -> out[:, 64:128)
    k_conv_mma<32, 64, 1, 1, 0><<<blocks, 256, SM_C64>>>(h1, midxT, wp + WP11_OFF, b11, x, out);
}

// round 16
// speedup vs baseline: 3.3484x; 1.0749x over previous
#include <cuda_runtime.h>
#include <cuda_fp16.h>
#include <stdint.h>

#define NPTS 500000
#define KK 27

// Scratch (allocation-free rule: __device__ globals)
__device__ __half g_xh [(size_t)NPTS * 128];  // fp16 x
__device__ __half g_h0 [NPTS * 32];
__device__ __half g_h0c[NPTS * 32];
__device__ __half g_h1 [NPTS * 32];
__device__ int    g_midxT[(size_t)KK * NPTS]; // transposed masked idx: [k][p]

// Permuted fp16 weights, m16n8k16-fragment-ordered, channel-consecutive:
//   slot s = ((k*PAIRS + pr)*NTS + nt)*32 + lane, uint2 =
//   { half2(W[c0],W[c0+1]), half2(W[c0+2],W[c0+3]) },  c0 = pr*16 + 4*(lane&3),
//   col = nt*8 + (lane>>2).
#define WP10_OFF 0
#define WP01_OFF 27648
#define WP11_OFF (27648 + 6912)
#define WP00_OFF (27648 + 6912 + 13824)
#define WP02_OFF (27648 + 6912 + 13824 + 1024)
__device__ uint2 g_wperm[27648 + 6912 + 13824 + 1024 + 512];

// ---------------------------------------------------------------------------
__device__ __forceinline__ uint32_t h2bits(__half2 h) {
    return *reinterpret_cast<uint32_t*>(&h);
}

__device__ __forceinline__ void mma_16n8k16(float* c, uint32_t a0, uint32_t a1,
                                            uint32_t a2, uint32_t a3,
                                            uint32_t b0, uint32_t b1) {
    asm volatile(
        "mma.sync.aligned.m16n8k16.row.col.f32.f16.f16.f32 "
        "{%0,%1,%2,%3}, {%4,%5,%6,%7}, {%8,%9}, {%0,%1,%2,%3};"
        : "+f"(c[0]), "+f"(c[1]), "+f"(c[2]), "+f"(c[3])
        : "r"(a0), "r"(a1), "r"(a2), "r"(a3), "r"(b0), "r"(b1));
}

// ---------------------------------------------------------------------------
// x -> fp16 prepass
// ---------------------------------------------------------------------------
__global__ __launch_bounds__(256) void k_cvt_x(const float4* __restrict__ x,
                                               uint2* __restrict__ xh)
{
    const int i = blockIdx.x * 256 + threadIdx.x;
    if (i >= NPTS * 32) return;
    float4 v = x[i];
    uint2 q;
    q.x = h2bits(__floats2half2_rn(v.x, v.y));
    q.y = h2bits(__floats2half2_rn(v.z, v.w));
    xh[i] = q;
}

// ---------------------------------------------------------------------------
// Weight permutation prep (channel-consecutive fragment layout, KKT taps).
// ---------------------------------------------------------------------------
template <int CIN, int COUT, int KKT>
__global__ void k_permW(const float* __restrict__ W, uint2* __restrict__ dst)
{
    const int PAIRS = CIN / 16, NTS = COUT / 8;
    const int total = KKT * PAIRS * NTS * 32;
    const int s = blockIdx.x * 256 + threadIdx.x;
    if (s >= total) return;
    const int lane = s & 31;
    int t = s >> 5;
    const int nt = t % NTS; t /= NTS;
    const int pr = t % PAIRS; t /= PAIRS;
    const int k = t;
    const int four = lane & 3, grp = lane >> 2;
    const int col = nt * 8 + grp;
    const int c0 = pr * 16 + 4 * four;
    const size_t base = (size_t)k * CIN * COUT + col;
    uint2 v;
    v.x = h2bits(__floats2half2_rn(W[base + (size_t)(c0)     * COUT],
                                   W[base + (size_t)(c0 + 1) * COUT]));
    v.y = h2bits(__floats2half2_rn(W[base + (size_t)(c0 + 2) * COUT],
                                   W[base + (size_t)(c0 + 3) * COUT]));
    dst[s] = v;
}

// ---------------------------------------------------------------------------
// Masked-neighbor transpose prep: midxT[k][p] = mask[p][k] ? nbr[p][k] : -1.
// ---------------------------------------------------------------------------
__global__ __launch_bounds__(256) void k_midx(const int* __restrict__ nbr,
                                              const int* __restrict__ mask,
                                              int* __restrict__ midxT)
{
    __shared__ int tile[128 * KK];
    const int tid = threadIdx.x;
    const int pbase = blockIdx.x * 128;
    for (int i = tid; i < 128 * KK; i += 256) {
        const int p = pbase + i / KK;
        int v = -1;
        if (p < NPTS) {
            const size_t g = (size_t)pbase * KK + i;
            if (mask[g] != 0) v = nbr[g];
        }
        tile[i] = v;
    }
    __syncthreads();
    for (int i = tid; i < 128 * KK; i += 256) {
        const int k = i >> 7, j = i & 127;
        if (pbase + j < NPTS)
            midxT[(size_t)k * NPTS + pbase + j] = tile[j * KK + k];
    }
}

// ---------------------------------------------------------------------------
// Unified sparse-conv GEMM via mma.sync fp16.
// Block: 256 threads = 8 warps; 256 points/block; warp owns 32 points.
// ALLK=1: all KK B slabs resident in smem, NO k-loop barriers, idx from gmem.
// ALLK=0: double-buffered B, one barrier per k; GATHER idx slab staged in
//         smem up-front (removes per-tap global idx latency from the chain).
// MODE 0: fp16 out = relu(acc+b).  MODE 1/2: f32 out cols [64,128)/[0,64)
//         = acc + b + x residual.
// ---------------------------------------------------------------------------
template <int CIN, int COUT, int MODE, int GATHER, int ALLK>
__global__ __launch_bounds__(256) void k_conv_mma(
    const __half* __restrict__ f, const int* __restrict__ midxT,
    const uint2* __restrict__ Wp, const float* __restrict__ b,
    const float* __restrict__ x, void* __restrict__ outv)
{
    constexpr int PAIRS = CIN / 16, NTS = COUT / 8;
    constexpr int KT    = GATHER ? KK : 1;
    constexpr int slabN = PAIRS * NTS * 32;   // uint2 per k
    constexpr int NB    = ALLK ? KT : 2;
    constexpr bool MIDX_S = (GATHER && !ALLK);

    extern __shared__ __align__(16) char smraw[];
    uint2* Bs     = (uint2*)smraw;                  // NB * slabN
    float* bs     = (float*)(Bs + NB * slabN);      // COUT
    int*   midx_s = (int*)(bs + COUT);              // [KT][256] if MIDX_S

    const int tid  = threadIdx.x;
    const int warp = tid >> 5;
    const int lane = tid & 31;
    const int grp  = lane >> 2;
    const int four = lane & 3;

    if (tid < COUT) bs[tid] = b[tid];

    const int pbase = blockIdx.x * 256;

    // initial B staging (+ midx slab)
    if (ALLK) {
        for (int i = tid; i < KT * slabN; i += 256) Bs[i] = Wp[i];
    } else {
        for (int i = tid; i < slabN; i += 256) Bs[i] = Wp[i];   // k=0 -> buf0
    }
    if (MIDX_S) {
        for (int i = tid; i < KT * 256; i += 256) {
            const int k = i >> 8, j = i & 255;
            const int p = pbase + j;
            midx_s[i] = (p < NPTS) ? __ldg(midxT + (size_t)k * NPTS + p) : -1;
        }
    }
    __syncthreads();

    const int lr = warp * 32 + grp;           // lane's rows: lr+{0,8,16,24}

    float acc0[NTS][4], acc1[NTS][4];
#pragma unroll
    for (int nt = 0; nt < NTS; nt++)
#pragma unroll
        for (int j = 0; j < 4; j++) { acc0[nt][j] = 0.f; acc1[nt][j] = 0.f; }

    for (int k = 0; k < KT; k++) {
        const uint2* Bk = Bs + (ALLK ? k : (k & 1)) * slabN;
        // stage next slab into the other buffer (no sync yet)
        if (!ALLK && k + 1 < KT) {
            uint2* Bn = Bs + ((k + 1) & 1) * slabN;
            for (int i = tid; i < slabN; i += 256)
                Bn[i] = Wp[(size_t)(k + 1) * slabN + i];
        }

        int idx[4];
#pragma unroll
        for (int r = 0; r < 4; r++) {
            const int p = pbase + lr + r * 8;
            if (MIDX_S)       idx[r] = midx_s[k * 256 + lr + r * 8];
            else if (GATHER)  idx[r] = (p < NPTS) ? __ldg(midxT + (size_t)k * NPTS + p) : -1;
            else              idx[r] = (p < NPTS) ? p : NPTS - 1;   // clamp
        }
        const uint2* rows[4];
#pragma unroll
        for (int r = 0; r < 4; r++)
            rows[r] = reinterpret_cast<const uint2*>(
                f + (size_t)(idx[r] < 0 ? 0 : idx[r]) * CIN);

        // 2-pr batches: 8 independent loads in flight, then MMAs
#pragma unroll
        for (int h = 0; h < PAIRS / 2; h++) {
            uint2 A[2][4];
#pragma unroll
            for (int j = 0; j < 2; j++)
#pragma unroll
                for (int r = 0; r < 4; r++) {
                    if (!GATHER || idx[r] >= 0)
                        A[j][r] = __ldg(rows[r] + (h * 2 + j) * 4 + four);
                    else
                        A[j][r] = make_uint2(0u, 0u);
                }
#pragma unroll
            for (int j = 0; j < 2; j++) {
                const int pr = h * 2 + j;
#pragma unroll
                for (int nt = 0; nt < NTS; nt++) {
                    const uint2 B = Bk[(pr * NTS + nt) * 32 + lane];
                    mma_16n8k16(acc0[nt], A[j][0].x, A[j][1].x, A[j][0].y, A[j][1].y, B.x, B.y);
                    mma_16n8k16(acc1[nt], A[j][2].x, A[j][3].x, A[j][2].y, A[j][3].y, B.x, B.y);
                }
            }
        }
        if (!ALLK && k + 1 < KT) __syncthreads();
    }

    // epilogue: acc0 -> rows lr, lr+8 ; acc1 -> rows lr+16, lr+24
#pragma unroll
    for (int t = 0; t < 2; t++) {
#pragma unroll
        for (int half = 0; half < 2; half++) {
            const int p = pbase + lr + t * 16 + half * 8;
            if (p >= NPTS) continue;
#pragma unroll
            for (int nt = 0; nt < NTS; nt++) {
                const float c0 = (t == 0) ? acc0[nt][half * 2]     : acc1[nt][half * 2];
                const float c1 = (t == 0) ? acc0[nt][half * 2 + 1] : acc1[nt][half * 2 + 1];
                const int col = nt * 8 + 2 * four;
                if (MODE == 0) {
                    uint32_t v = h2bits(__floats2half2_rn(fmaxf(c0 + bs[col], 0.f),
                                                          fmaxf(c1 + bs[col + 1], 0.f)));
                    *reinterpret_cast<uint32_t*>((__half*)outv + (size_t)p * COUT + col) = v;
                } else {
                    const int oc = (MODE == 1) ? (64 + col) : col;
                    const size_t a = (size_t)p * 128 + oc;
                    float2 xr = *reinterpret_cast<const float2*>(x + a);
                    float2 v = {c0 + bs[col] + xr.x, c1 + bs[col + 1] + xr.y};
                    *reinterpret_cast<float2*>((float*)outv + a) = v;
                }
            }
        }
    }
}

// ---------------------------------------------------------------------------
extern "C" void kernel_launch(void* const* d_in, const int* in_sizes, int n_in,
                              void* d_out, int out_size)
{
    const float* x    = (const float*)d_in[0];
    const int*   nbr  = (const int*)  d_in[1];
    const int*   mask = (const int*)  d_in[2];   // bool -> int32 in harness
    const float* W00  = (const float*)d_in[3];
    const float* b00  = (const float*)d_in[4];
    const float* W01  = (const float*)d_in[5];
    const float* b01  = (const float*)d_in[6];
    const float* W02  = (const float*)d_in[7];
    const float* b02  = (const float*)d_in[8];
    const float* W10  = (const float*)d_in[9];
    const float* b10  = (const float*)d_in[10];
    const float* W11  = (const float*)d_in[11];
    const float* b11  = (const float*)d_in[12];
    float* out = (float*)d_out;

    __half *xh, *h0, *h0c, *h1;
    int* midxT;
    uint2* wp;
    cudaGetSymbolAddress((void**)&xh,    g_xh);
    cudaGetSymbolAddress((void**)&h0,    g_h0);
    cudaGetSymbolAddress((void**)&h0c,   g_h0c);
    cudaGetSymbolAddress((void**)&h1,    g_h1);
    cudaGetSymbolAddress((void**)&midxT, g_midxT);
    cudaGetSymbolAddress((void**)&wp,    g_wperm);

    // dynamic smem: NB*slabN*8 + COUT*4 (+ KK*256*4 for staged midx)
    const int MIDX_B   = KK * 256 * 4;                    // 27648
    const int SM_BIG_G = 2 * 1024 * 8 + 128 + MIDX_B;     // 44160: 128->32 gather
    const int SM_BIG   = 2 * 1024 * 8 + 128;              // 16512: 128->32 1x1
    const int SM_ALLK  = KK * 256 * 8 + 128;              // 55424: 32->32 all-k conv
    const int SM_C64_G = 2 * 512 * 8 + 256 + MIDX_B;      // 36160: 32->64 gather
    const int SM_C64   = 2 * 512 * 8 + 256;               // 8448:  32->64 1x1
    cudaFuncSetAttribute(k_conv_mma<32, 32, 0, 1, 1>,
                         cudaFuncAttributeMaxDynamicSharedMemorySize, SM_ALLK);

    const int blocks  = (NPTS + 255) / 256;   // conv kernels: 256 points/block
    const int mblocks = (NPTS + 127) / 128;   // midx transpose tiles

    // launches 0..2: prep needed by the big conv
    k_permW<128, 32, KK><<<(27648 + 255) / 256, 256>>>(W10, wp + WP10_OFF);
    k_cvt_x<<<(NPTS * 32 + 255) / 256, 256>>>((const float4*)x, (uint2*)xh);
    k_midx<<<mblocks, 256>>>(nbr, mask, midxT);

    // launch 3 (ncu capture slot): branch 1 heavy conv3 -> relu
    k_conv_mma<128, 32, 0, 1, 0><<<blocks, 256, SM_BIG_G>>>(xh, midxT, wp + WP10_OFF, b10, nullptr, h1);

    // remaining prep
    k_permW< 32, 32, KK><<<( 6912 + 255) / 256, 256>>>(W01, wp + WP01_OFF);
    k_permW< 32, 64, KK><<<(13824 + 255) / 256, 256>>>(W11, wp + WP11_OFF);
    k_permW<128, 32,  1><<<( 1024 + 255) / 256, 256>>>(W00, wp + WP00_OFF);
    k_permW< 32, 64,  1><<<(  512 + 255) / 256, 256>>>(W02, wp + WP02_OFF);

    // branch 0: 1x1 -> relu
    k_conv_mma<128, 32, 0, 0, 0><<<blocks, 256, SM_BIG>>>(xh, nullptr, wp + WP00_OFF, b00, nullptr, h0);
    // branch 0: 3x3 -> relu  (all-k B resident, barrier-free k loop)
    k_conv_mma<32, 32, 0, 1, 1><<<blocks, 256, SM_ALLK>>>(h0, midxT, wp + WP01_OFF, b01, nullptr, h0c);
    // branch 0 tail: 1x1 + bias + residual -> out[:, 0:64)
    k_conv_mma<32, 64, 2, 0, 0><<<blocks, 256, SM_C64>>>(h0c, nullptr, wp + WP02_OFF, b02, x, out);
    // branch 1 tail: 3x3 + bias + residual -> out[:, 64:128)
    k_conv_mma<32, 64, 1, 1, 0><<<blocks, 256, SM_C64_G>>>(h1, midxT, wp + WP11_OFF, b11, x, out);
}